// round 14
// baseline (speedup 1.0000x reference)
#include <cuda_runtime.h>
#include <cuda_bf16.h>
#include <stdint.h>

#define SEQS 4096
#define NCTA 2048
#define THREADS 256

// Dynamic smem layout (bytes):
//  [0,34816)        f32 stage[128][68] (x staging / xres spill) -> bf16 scr[128][136] q|attn (0..63), k (64..127)
//  [34816,53248)    bf16 vt[2][8][8][72]  V transposed per seq/head
//  [53248,86016)    WA: qkv packed (24576B) + proj packed (8192B); later reused for fc2 packed (32768B)
//  [86016,102400)   WB: fc1 half-buffer (16384B, double-buffered h0 -> h1)
#define ST_S 68
#define SCR_S 136
#define VT_S 72
#define VT_OFF 34816
#define WA_OFF 53248
#define WB_OFF 86016
#define SMEM_BYTES 102400

// q pre-scale: (1/8) * log2(e); softmax uses exp2
#define QSCALE 0.1803368801111204f

// Fragment-packed bf16 weights (same layout as prior rounds):
//   [nt][u][lane][c]; kk = 2u + (c>>1), j = c&1; n = nt*8 + (lane>>2); k = kk*16 + 2*(lane&3) + 8*j
__device__ __align__(16) uint32_t g_wqkvP[24 * 2 * 32 * 4];   // 24576 B
__device__ __align__(16) uint32_t g_projP[8 * 2 * 32 * 4];    // 8192 B
__device__ __align__(16) uint32_t g_fc1P[32 * 2 * 32 * 4];    // 32768 B
__device__ __align__(16) uint32_t g_fc2P[8 * 8 * 32 * 4];     // 32768 B

__device__ __forceinline__ uint32_t packbf(float lo, float hi) {
    __nv_bfloat162 t = __floats2bfloat162_rn(lo, hi);
    return *reinterpret_cast<uint32_t*>(&t);
}

__device__ __forceinline__ float ex2(float x) {
    float r; asm("ex2.approx.f32 %0, %1;" : "=f"(r) : "f"(x)); return r;
}

__device__ __forceinline__ uint32_t smem_u32(const void* p) {
    uint32_t a;
    asm("{ .reg .u64 t; cvta.to.shared.u64 t, %1; cvt.u32.u64 %0, t; }" : "=r"(a) : "l"(p));
    return a;
}

__device__ __forceinline__ void cp16(uint32_t dst, const void* src) {
    asm volatile("cp.async.cg.shared.global [%0], [%1], 16;" :: "r"(dst), "l"(src) : "memory");
}
#define CP_COMMIT() asm volatile("cp.async.commit_group;" ::: "memory")
#define CP_WAIT(n)  asm volatile("cp.async.wait_group %0;" :: "n"(n) : "memory")

__global__ void prep_kernel(const float* __restrict__ wq, const float* __restrict__ wk,
                            const float* __restrict__ wv, const float* __restrict__ projw,
                            const float* __restrict__ fc1w, const float* __restrict__ fc2w) {
    int stride = gridDim.x * blockDim.x;
    int t0 = blockIdx.x * blockDim.x + threadIdx.x;

    for (int idx = t0; idx < 24 * 2 * 32 * 4; idx += stride) {
        int c = idx & 3, lane = (idx >> 2) & 31, u = (idx >> 7) & 1, nt = idx >> 8;
        int kk = 2 * u + (c >> 1), j = c & 1;
        int n = nt * 8 + (lane >> 2);
        int kb = kk * 16 + 2 * (lane & 3) + 8 * j;
        float v0, v1;
        if (n < 64)       { int h = n >> 3, d = n & 7; v0 = wq[(h * 64 + kb) * 8 + d]; v1 = wq[(h * 64 + kb + 1) * 8 + d]; }
        else if (n < 128) { int m = n - 64;  int h = m >> 3, d = m & 7; v0 = wk[(h * 64 + kb) * 8 + d]; v1 = wk[(h * 64 + kb + 1) * 8 + d]; }
        else              { int m = n - 128; int h = m >> 3, d = m & 7; v0 = wv[(h * 64 + kb) * 8 + d]; v1 = wv[(h * 64 + kb + 1) * 8 + d]; }
        g_wqkvP[idx] = packbf(v0, v1);
    }
    for (int idx = t0; idx < 8 * 2 * 32 * 4; idx += stride) {
        int c = idx & 3, lane = (idx >> 2) & 31, u = (idx >> 7) & 1, nt = idx >> 8;
        int kk = 2 * u + (c >> 1), j = c & 1;
        int n = nt * 8 + (lane >> 2);
        int kb = kk * 16 + 2 * (lane & 3) + 8 * j;
        g_projP[idx] = packbf(projw[kb * 64 + n], projw[(kb + 1) * 64 + n]);
    }
    for (int idx = t0; idx < 32 * 2 * 32 * 4; idx += stride) {
        int c = idx & 3, lane = (idx >> 2) & 31, u = (idx >> 7) & 1, nt = idx >> 8;
        int kk = 2 * u + (c >> 1), j = c & 1;
        int n = nt * 8 + (lane >> 2);
        int kb = kk * 16 + 2 * (lane & 3) + 8 * j;
        g_fc1P[idx] = packbf(fc1w[kb * 256 + n], fc1w[(kb + 1) * 256 + n]);
    }
    for (int idx = t0; idx < 8 * 8 * 32 * 4; idx += stride) {
        int c = idx & 3, lane = (idx >> 2) & 31, u = (idx >> 7) & 7, nt = idx >> 10;
        int kk = 2 * u + (c >> 1), j = c & 1;
        int n = nt * 8 + (lane >> 2);
        int kb = kk * 16 + 2 * (lane & 3) + 8 * j;
        g_fc2P[idx] = packbf(fc2w[kb * 64 + n], fc2w[(kb + 1) * 64 + n]);
    }
}

__device__ __forceinline__ void mma16816(float* c, const uint32_t* a, const uint32_t* b) {
    asm volatile(
        "mma.sync.aligned.m16n8k16.row.col.f32.bf16.bf16.f32 "
        "{%0,%1,%2,%3}, {%4,%5,%6,%7}, {%8,%9}, {%0,%1,%2,%3};\n"
        : "+f"(c[0]), "+f"(c[1]), "+f"(c[2]), "+f"(c[3])
        : "r"(a[0]), "r"(a[1]), "r"(a[2]), "r"(a[3]), "r"(b[0]), "r"(b[1]));
}

__device__ __forceinline__ void mma1688(float* c, const uint32_t* a, uint32_t b) {
    asm volatile(
        "mma.sync.aligned.m16n8k8.row.col.f32.bf16.bf16.f32 "
        "{%0,%1,%2,%3}, {%4,%5}, {%6}, {%0,%1,%2,%3};\n"
        : "+f"(c[0]), "+f"(c[1]), "+f"(c[2]), "+f"(c[3])
        : "r"(a[0]), "r"(a[1]), "r"(b));
}

// Register LayerNorm over fragment-resident residual (rows m0+g, m0+g+8; 4-lane qd groups).
__device__ __forceinline__ void ln_frag(const float xres[2][8][2],
                                        const float* __restrict__ lnw,
                                        const float* __restrict__ lnb,
                                        int qd, uint32_t a[4][4]) {
    float s0 = 0.f, q0 = 0.f, s1 = 0.f, q1 = 0.f;
#pragma unroll
    for (int nt = 0; nt < 8; ++nt) {
#pragma unroll
        for (int e = 0; e < 2; ++e) {
            float v0 = xres[0][nt][e], v1 = xres[1][nt][e];
            s0 += v0; q0 = fmaf(v0, v0, q0);
            s1 += v1; q1 = fmaf(v1, v1, q1);
        }
    }
    s0 += __shfl_xor_sync(0xffffffffu, s0, 1); s0 += __shfl_xor_sync(0xffffffffu, s0, 2);
    q0 += __shfl_xor_sync(0xffffffffu, q0, 1); q0 += __shfl_xor_sync(0xffffffffu, q0, 2);
    s1 += __shfl_xor_sync(0xffffffffu, s1, 1); s1 += __shfl_xor_sync(0xffffffffu, s1, 2);
    q1 += __shfl_xor_sync(0xffffffffu, q1, 1); q1 += __shfl_xor_sync(0xffffffffu, q1, 2);
    float mu0 = s0 * 0.015625f, mu1 = s1 * 0.015625f;
    float rs0 = rsqrtf(q0 * 0.015625f - mu0 * mu0 + 1e-5f);
    float rs1 = rsqrtf(q1 * 0.015625f - mu1 * mu1 + 1e-5f);
#pragma unroll
    for (int kk = 0; kk < 4; ++kk) {
#pragma unroll
        for (int j = 0; j < 2; ++j) {
            int nt = 2 * kk + j;
            float2 wv = __ldg(reinterpret_cast<const float2*>(&lnw[nt * 8 + 2 * qd]));
            float2 bv = __ldg(reinterpret_cast<const float2*>(&lnb[nt * 8 + 2 * qd]));
            a[kk][2 * j]     = packbf((xres[0][nt][0] - mu0) * rs0 * wv.x + bv.x,
                                      (xres[0][nt][1] - mu0) * rs0 * wv.y + bv.y);
            a[kk][2 * j + 1] = packbf((xres[1][nt][0] - mu1) * rs1 * wv.x + bv.x,
                                      (xres[1][nt][1] - mu1) * rs1 * wv.y + bv.y);
        }
    }
}

__global__ __launch_bounds__(THREADS, 2) void block_kernel(
    const float* __restrict__ x,
    const float* __restrict__ ln1w, const float* __restrict__ ln1b,
    const float* __restrict__ projb,
    const float* __restrict__ ln2w, const float* __restrict__ ln2b,
    const float* __restrict__ fc1b, const float* __restrict__ fc2b,
    float* __restrict__ out)
{
    extern __shared__ char smraw[];
    float* stage       = reinterpret_cast<float*>(smraw);                    // [128][68] f32
    __nv_bfloat16* scr = reinterpret_cast<__nv_bfloat16*>(smraw);            // [128][136] (aliases stage)
    __nv_bfloat16* vt  = reinterpret_cast<__nv_bfloat16*>(smraw + VT_OFF);   // [2][8][8][72]

    const int tid  = threadIdx.x;
    const int w    = tid >> 5;
    const int lane = tid & 31;
    const int g    = lane >> 2;
    const int qd   = lane & 3;
    const int s    = blockIdx.x;          // covers seqs 2s, 2s+1
    const int seqw = w >> 2;              // GEMM-phase sequence of this warp
    const int m0   = seqw * 64 + (w & 3) * 16;   // row in 0..127

    const uint32_t sA = smem_u32(smraw + WA_OFF);
    const uint32_t sB = smem_u32(smraw + WB_OFF);

    // ---- prefetch group 0: qkv + proj -> WA ----
#pragma unroll
    for (int i = 0; i < 6; ++i)
        cp16(sA + (tid + i * 256) * 16, (const char*)g_wqkvP + (tid + i * 256) * 16);
#pragma unroll
    for (int i = 0; i < 2; ++i)
        cp16(sA + 24576 + (tid + i * 256) * 16, (const char*)g_projP + (tid + i * 256) * 16);
    CP_COMMIT();
    // ---- prefetch group 1: fc1 half 0 -> WB ----
#pragma unroll
    for (int i = 0; i < 4; ++i)
        cp16(sB + (tid + i * 256) * 16, (const char*)g_fc1P + (tid + i * 256) * 16);
    CP_COMMIT();

    // ---- stage x for both seqs ----
    {
        const float4* xg = reinterpret_cast<const float4*>(x + (size_t)s * 128 * 64);
        int row = tid >> 1, c0 = (tid & 1) * 32;
#pragma unroll
        for (int i = 0; i < 8; ++i) {
            float4 v = xg[row * 16 + (c0 >> 2) + i];
            *reinterpret_cast<float4*>(&stage[row * ST_S + c0 + 4 * i]) = v;
        }
    }
    __syncthreads();

    // ---- hoist residual into fragment registers ----
    float xres[2][8][2];
#pragma unroll
    for (int nt = 0; nt < 8; ++nt) {
        float2 v0 = *reinterpret_cast<const float2*>(&stage[(m0 + g)     * ST_S + nt * 8 + 2 * qd]);
        float2 v1 = *reinterpret_cast<const float2*>(&stage[(m0 + g + 8) * ST_S + nt * 8 + 2 * qd]);
        xres[0][nt][0] = v0.x; xres[0][nt][1] = v0.y;
        xres[1][nt][0] = v1.x; xres[1][nt][1] = v1.y;
    }
    CP_WAIT(1);        // WA (qkv+proj) resident
    __syncthreads();   // stage dead; WA visible

    // ---- LN1 (registers) -> QKV A fragments ----
    uint32_t a[4][4];
    ln_frag(xres, ln1w, ln1b, qd, a);

    // ---- QKV GEMM (weights from WA): q(pre-scaled)/k -> scr, v -> vt ----
    {
        const int t0r = (w & 3) * 16;   // row-within-seq base for V transpose
#pragma unroll 4
        for (int nt = 0; nt < 24; ++nt) {
            uint4 b01 = *reinterpret_cast<const uint4*>(smraw + WA_OFF + (nt * 64 + lane) * 16);
            uint4 b23 = *reinterpret_cast<const uint4*>(smraw + WA_OFF + (nt * 64 + 32 + lane) * 16);
            float c[4] = {0.f, 0.f, 0.f, 0.f};
            mma16816(c, a[0], &b01.x);
            mma16816(c, a[1], &b01.z);
            mma16816(c, a[2], &b23.x);
            mma16816(c, a[3], &b23.z);
            if (nt < 8) {
                int n0 = nt * 8;
                *reinterpret_cast<uint32_t*>(&scr[(m0 + g)     * SCR_S + n0 + 2 * qd]) =
                    packbf(c[0] * QSCALE, c[1] * QSCALE);
                *reinterpret_cast<uint32_t*>(&scr[(m0 + g + 8) * SCR_S + n0 + 2 * qd]) =
                    packbf(c[2] * QSCALE, c[3] * QSCALE);
            } else if (nt < 16) {
                int n0 = 64 + (nt - 8) * 8;
                *reinterpret_cast<uint32_t*>(&scr[(m0 + g)     * SCR_S + n0 + 2 * qd]) = packbf(c[0], c[1]);
                *reinterpret_cast<uint32_t*>(&scr[(m0 + g + 8) * SCR_S + n0 + 2 * qd]) = packbf(c[2], c[3]);
            } else {
                int head = nt - 16;
                __nv_bfloat16* vh = vt + (seqw * 8 + head) * 8 * VT_S;
                vh[(2 * qd)     * VT_S + t0r + g]     = __float2bfloat16(c[0]);
                vh[(2 * qd + 1) * VT_S + t0r + g]     = __float2bfloat16(c[1]);
                vh[(2 * qd)     * VT_S + t0r + g + 8] = __float2bfloat16(c[2]);
                vh[(2 * qd + 1) * VT_S + t0r + g + 8] = __float2bfloat16(c[3]);
            }
        }
    }
    __syncthreads();   // qkv weights dead

    // ---- prefetch group 2: fc2 first 24KB -> WA[0,24576) (window = attention + proj) ----
#pragma unroll
    for (int i = 0; i < 6; ++i)
        cp16(sA + (tid + i * 256) * 16, (const char*)g_fc2P + (tid + i * 256) * 16);
    CP_COMMIT();

    // ---- attention: warp handles head-seqs 2w, 2w+1 (16 total); attn-out IN PLACE over q ----
#pragma unroll
    for (int hh = 0; hh < 2; ++hh) {
        const int hs = w * 2 + hh;            // 0..15
        const int aseq = hs >> 3, hd = hs & 7;
        const int qb = aseq * 64;             // scr row base for this seq
        const int qcol = hd * 8, kcol = 64 + hd * 8;
        const __nv_bfloat16* vh = vt + (aseq * 8 + hd) * 8 * VT_S;
#pragma unroll
        for (int mt = 0; mt < 4; ++mt) {
            const int t0 = mt * 16;
            const int ntm = 2 * mt + 1;
            uint32_t aq[2];
            aq[0] = *reinterpret_cast<const uint32_t*>(&scr[(qb + t0 + g)     * SCR_S + qcol + 2 * qd]);
            aq[1] = *reinterpret_cast<const uint32_t*>(&scr[(qb + t0 + g + 8) * SCR_S + qcol + 2 * qd]);
            float sc[8][4];
#pragma unroll
            for (int nt = 0; nt < 8; ++nt) {
                if (nt > ntm) continue;
                sc[nt][0] = sc[nt][1] = sc[nt][2] = sc[nt][3] = 0.f;
                uint32_t bk = *reinterpret_cast<const uint32_t*>(&scr[(qb + nt * 8 + g) * SCR_S + kcol + 2 * qd]);
                mma1688(sc[nt], aq, bk);
            }
            const int rlo = t0 + g, rhi = t0 + g + 8;
            float slo = 0.f, shi = 0.f;
#pragma unroll
            for (int nt = 0; nt < 8; ++nt) {
                if (nt > ntm) continue;
#pragma unroll
                for (int e = 0; e < 2; ++e) {
                    int col = nt * 8 + 2 * qd + e;
                    float p0 = (col <= rlo) ? ex2(sc[nt][e])     : 0.f;
                    float p1 = (col <= rhi) ? ex2(sc[nt][2 + e]) : 0.f;
                    sc[nt][e] = p0; sc[nt][2 + e] = p1;
                    slo += p0; shi += p1;
                }
            }
            slo += __shfl_xor_sync(0xffffffffu, slo, 1);
            slo += __shfl_xor_sync(0xffffffffu, slo, 2);
            shi += __shfl_xor_sync(0xffffffffu, shi, 1);
            shi += __shfl_xor_sync(0xffffffffu, shi, 2);
            float acc[4] = {0.f, 0.f, 0.f, 0.f};
#pragma unroll
            for (int kc = 0; kc < 4; ++kc) {
                if (kc > mt) continue;
                uint32_t pa[4];
                pa[0] = packbf(sc[2 * kc][0],     sc[2 * kc][1]);
                pa[1] = packbf(sc[2 * kc][2],     sc[2 * kc][3]);
                pa[2] = packbf(sc[2 * kc + 1][0], sc[2 * kc + 1][1]);
                pa[3] = packbf(sc[2 * kc + 1][2], sc[2 * kc + 1][3]);
                const int sb = kc * 16;
                uint32_t b[2];
                b[0] = *reinterpret_cast<const uint32_t*>(&vh[g * VT_S + sb + 2 * qd]);
                b[1] = *reinterpret_cast<const uint32_t*>(&vh[g * VT_S + sb + 2 * qd + 8]);
                mma16816(acc, pa, b);
            }
            float ilo = 1.f / slo, ihi = 1.f / shi;
            *reinterpret_cast<uint32_t*>(&scr[(qb + t0 + g)     * SCR_S + qcol + 2 * qd]) = packbf(acc[0] * ilo, acc[1] * ilo);
            *reinterpret_cast<uint32_t*>(&scr[(qb + t0 + g + 8) * SCR_S + qcol + 2 * qd]) = packbf(acc[2] * ihi, acc[3] * ihi);
        }
    }
    __syncthreads();

    // ---- proj + residual into xres (registers); weights from WA[24576,32768) ----
    {
        uint32_t ap[4][4];
#pragma unroll
        for (int kk = 0; kk < 4; ++kk) {
            int k0 = kk * 16;
            ap[kk][0] = *reinterpret_cast<const uint32_t*>(&scr[(m0 + g)     * SCR_S + k0 + 2 * qd]);
            ap[kk][1] = *reinterpret_cast<const uint32_t*>(&scr[(m0 + g + 8) * SCR_S + k0 + 2 * qd]);
            ap[kk][2] = *reinterpret_cast<const uint32_t*>(&scr[(m0 + g)     * SCR_S + k0 + 2 * qd + 8]);
            ap[kk][3] = *reinterpret_cast<const uint32_t*>(&scr[(m0 + g + 8) * SCR_S + k0 + 2 * qd + 8]);
        }
#pragma unroll
        for (int nt = 0; nt < 8; ++nt) {
            uint4 b01 = *reinterpret_cast<const uint4*>(smraw + WA_OFF + 24576 + (nt * 64 + lane) * 16);
            uint4 b23 = *reinterpret_cast<const uint4*>(smraw + WA_OFF + 24576 + (nt * 64 + 32 + lane) * 16);
            float c[4] = {0.f, 0.f, 0.f, 0.f};
            mma16816(c, ap[0], &b01.x);
            mma16816(c, ap[1], &b01.z);
            mma16816(c, ap[2], &b23.x);
            mma16816(c, ap[3], &b23.z);
            float2 pb = __ldg(reinterpret_cast<const float2*>(&projb[nt * 8 + 2 * qd]));
            xres[0][nt][0] += c[0] + pb.x; xres[0][nt][1] += c[1] + pb.y;
            xres[1][nt][0] += c[2] + pb.x; xres[1][nt][1] += c[3] + pb.y;
        }
    }
    __syncthreads();   // proj weights + scr reads done

    // ---- prefetch group 3: fc2 last 8KB -> WA[24576,32768) ----
#pragma unroll
    for (int i = 0; i < 2; ++i)
        cp16(sA + 24576 + (tid + i * 256) * 16, (const char*)g_fc2P + 24576 + (tid + i * 256) * 16);
    CP_COMMIT();

    // ---- LN2 (registers) -> fc1 A fragments ----
    uint32_t a2[4][4];
    ln_frag(xres, ln2w, ln2b, qd, a2);

    // ---- spill xres to stage (scr dead; self-read only, no barrier needed) ----
#pragma unroll
    for (int nt = 0; nt < 8; ++nt) {
        float2 v0, v1;
        v0.x = xres[0][nt][0]; v0.y = xres[0][nt][1];
        v1.x = xres[1][nt][0]; v1.y = xres[1][nt][1];
        *reinterpret_cast<float2*>(&stage[(m0 + g)     * ST_S + nt * 8 + 2 * qd]) = v0;
        *reinterpret_cast<float2*>(&stage[(m0 + g + 8) * ST_S + nt * 8 + 2 * qd]) = v1;
    }

    CP_WAIT(0);        // fc1.h0 (WB) + fc2 (WA) resident
    __syncthreads();

    // ---- fc phase, double-buffered fc1 halves in WB ----
    float cfc2[8][4];
#pragma unroll
    for (int i = 0; i < 8; ++i) { cfc2[i][0] = cfc2[i][1] = cfc2[i][2] = cfc2[i][3] = 0.f; }

    uint32_t apk8[8][4];
    // ===== half 0: fc1 nt 0..15 from WB =====
#pragma unroll
    for (int kkL = 0; kkL < 8; ++kkL) {
#pragma unroll
        for (int half = 0; half < 2; ++half) {
            int nt = 2 * kkL + half;
            uint4 b01 = *reinterpret_cast<const uint4*>(smraw + WB_OFF + (nt * 64 + lane) * 16);
            uint4 b23 = *reinterpret_cast<const uint4*>(smraw + WB_OFF + (nt * 64 + 32 + lane) * 16);
            float c[4] = {0.f, 0.f, 0.f, 0.f};
            mma16816(c, a2[0], &b01.x);
            mma16816(c, a2[1], &b01.z);
            mma16816(c, a2[2], &b23.x);
            mma16816(c, a2[3], &b23.z);
            float2 fb = __ldg(reinterpret_cast<const float2*>(&fc1b[nt * 8 + 2 * qd]));
            apk8[kkL][2 * half]     = packbf(fmaxf(c[0] + fb.x, 0.f), fmaxf(c[1] + fb.y, 0.f));
            apk8[kkL][2 * half + 1] = packbf(fmaxf(c[2] + fb.x, 0.f), fmaxf(c[3] + fb.y, 0.f));
        }
    }
    __syncthreads();   // all warps done reading fc1.h0 from WB
    // prefetch fc1 half 1 -> WB (covered by fc2-partial h0 compute)
#pragma unroll
    for (int i = 0; i < 4; ++i)
        cp16(sB + (tid + i * 256) * 16, (const char*)g_fc1P + 16384 + (tid + i * 256) * 16);
    CP_COMMIT();
    // fc2 partial, h2 = 0 (u groups 0..3)
#pragma unroll
    for (int nt2 = 0; nt2 < 8; ++nt2) {
#pragma unroll
        for (int u = 0; u < 4; ++u) {
            uint4 bb = *reinterpret_cast<const uint4*>(
                smraw + WA_OFF + ((nt2 * 8 + u) * 32 + lane) * 16);
            mma16816(cfc2[nt2], apk8[2 * u],     &bb.x);
            mma16816(cfc2[nt2], apk8[2 * u + 1], &bb.z);
        }
    }
    CP_WAIT(0);
    __syncthreads();   // fc1.h1 resident

    // ===== half 1: fc1 nt 16..31 from WB =====
#pragma unroll
    for (int kkL = 0; kkL < 8; ++kkL) {
#pragma unroll
        for (int half = 0; half < 2; ++half) {
            int nt = 16 + 2 * kkL + half;
            uint4 b01 = *reinterpret_cast<const uint4*>(smraw + WB_OFF + ((nt - 16) * 64 + lane) * 16);
            uint4 b23 = *reinterpret_cast<const uint4*>(smraw + WB_OFF + ((nt - 16) * 64 + 32 + lane) * 16);
            float c[4] = {0.f, 0.f, 0.f, 0.f};
            mma16816(c, a2[0], &b01.x);
            mma16816(c, a2[1], &b01.z);
            mma16816(c, a2[2], &b23.x);
            mma16816(c, a2[3], &b23.z);
            float2 fb = __ldg(reinterpret_cast<const float2*>(&fc1b[nt * 8 + 2 * qd]));
            apk8[kkL][2 * half]     = packbf(fmaxf(c[0] + fb.x, 0.f), fmaxf(c[1] + fb.y, 0.f));
            apk8[kkL][2 * half + 1] = packbf(fmaxf(c[2] + fb.x, 0.f), fmaxf(c[3] + fb.y, 0.f));
        }
    }
    // fc2 partial, h2 = 1 (u groups 4..7)
#pragma unroll
    for (int nt2 = 0; nt2 < 8; ++nt2) {
#pragma unroll
        for (int u = 0; u < 4; ++u) {
            uint4 bb = *reinterpret_cast<const uint4*>(
                smraw + WA_OFF + ((nt2 * 8 + 4 + u) * 32 + lane) * 16);
            mma16816(cfc2[nt2], apk8[2 * u],     &bb.x);
            mma16816(cfc2[nt2], apk8[2 * u + 1], &bb.z);
        }
    }

    // ---- fc2 epilogue: + bias + residual (from smem spill) -> out ----
    {
#pragma unroll
        for (int nt = 0; nt < 8; ++nt) {
            int c0 = nt * 8 + 2 * qd;
            float2 fb = __ldg(reinterpret_cast<const float2*>(&fc2b[c0]));
            float2 x0 = *reinterpret_cast<const float2*>(&stage[(m0 + g)     * ST_S + c0]);
            float2 x1 = *reinterpret_cast<const float2*>(&stage[(m0 + g + 8) * ST_S + c0]);
            float2 o0, o1;
            o0.x = cfc2[nt][0] + fb.x + x0.x;
            o0.y = cfc2[nt][1] + fb.y + x0.y;
            o1.x = cfc2[nt][2] + fb.x + x1.x;
            o1.y = cfc2[nt][3] + fb.y + x1.y;
            *reinterpret_cast<float2*>(out + ((size_t)s * 128 + m0 + g)     * 64 + c0) = o0;
            *reinterpret_cast<float2*>(out + ((size_t)s * 128 + m0 + g + 8) * 64 + c0) = o1;
        }
    }
}

extern "C" void kernel_launch(void* const* d_in, const int* in_sizes, int n_in,
                              void* d_out, int out_size) {
    (void)in_sizes; (void)n_in; (void)out_size;
    const float* x     = (const float*)d_in[0];
    const float* ln1w  = (const float*)d_in[1];
    const float* ln1b  = (const float*)d_in[2];
    const float* wq    = (const float*)d_in[3];
    const float* wk    = (const float*)d_in[4];
    const float* wv    = (const float*)d_in[5];
    const float* projw = (const float*)d_in[6];
    const float* projb = (const float*)d_in[7];
    const float* ln2w  = (const float*)d_in[8];
    const float* ln2b  = (const float*)d_in[9];
    const float* fc1w  = (const float*)d_in[10];
    const float* fc1b  = (const float*)d_in[11];
    const float* fc2w  = (const float*)d_in[12];
    const float* fc2b  = (const float*)d_in[13];

    cudaFuncSetAttribute(block_kernel, cudaFuncAttributeMaxDynamicSharedMemorySize, SMEM_BYTES);
    cudaFuncSetAttribute(block_kernel, cudaFuncAttributePreferredSharedMemoryCarveout, 100);

    prep_kernel<<<32, 256>>>(wq, wk, wv, projw, fc1w, fc2w);
    block_kernel<<<NCTA, THREADS, SMEM_BYTES>>>(x, ln1w, ln1b, projb, ln2w, ln2b,
                                                fc1b, fc2b, (float*)d_out);
}

// round 15
// speedup vs baseline: 1.0002x; 1.0002x over previous
#include <cuda_runtime.h>
#include <cuda_bf16.h>
#include <stdint.h>

#define SEQS 4096
#define NCTA 2048
#define THREADS 256

// Dynamic smem layout (bytes):
//  [0,34816)        f32 stage[128][68] (x staging / xres spill) -> bf16 scr[128][136] q|attn (0..63), k (64..127)
//  [34816,53248)    bf16 vt[2][8][8][72]  V transposed per seq/head
//  [53248,86016)    WA: qkv packed (24576B) + proj packed (8192B); later reused for fc2 packed (32768B)
//  [86016,102400)   WB: fc1 half-buffer (16384B, double-buffered h0 -> h1)
#define ST_S 68
#define SCR_S 136
#define VT_S 72
#define VT_OFF 34816
#define WA_OFF 53248
#define WB_OFF 86016
#define SMEM_BYTES 102400

// q pre-scale: (1/8) * log2(e); softmax uses exp2
#define QSCALE 0.1803368801111204f

// Fragment-packed bf16 weights (same layout as prior rounds):
//   [nt][u][lane][c]; kk = 2u + (c>>1), j = c&1; n = nt*8 + (lane>>2); k = kk*16 + 2*(lane&3) + 8*j
__device__ __align__(16) uint32_t g_wqkvP[24 * 2 * 32 * 4];   // 24576 B
__device__ __align__(16) uint32_t g_projP[8 * 2 * 32 * 4];    // 8192 B
__device__ __align__(16) uint32_t g_fc1P[32 * 2 * 32 * 4];    // 32768 B
__device__ __align__(16) uint32_t g_fc2P[8 * 8 * 32 * 4];     // 32768 B

__device__ __forceinline__ uint32_t packbf(float lo, float hi) {
    __nv_bfloat162 t = __floats2bfloat162_rn(lo, hi);
    return *reinterpret_cast<uint32_t*>(&t);
}

__device__ __forceinline__ float ex2(float x) {
    float r; asm("ex2.approx.f32 %0, %1;" : "=f"(r) : "f"(x)); return r;
}

__device__ __forceinline__ uint32_t smem_u32(const void* p) {
    uint32_t a;
    asm("{ .reg .u64 t; cvta.to.shared.u64 t, %1; cvt.u32.u64 %0, t; }" : "=r"(a) : "l"(p));
    return a;
}

__device__ __forceinline__ void cp16(uint32_t dst, const void* src) {
    asm volatile("cp.async.cg.shared.global [%0], [%1], 16;" :: "r"(dst), "l"(src) : "memory");
}
#define CP_COMMIT() asm volatile("cp.async.commit_group;" ::: "memory")
#define CP_WAIT(n)  asm volatile("cp.async.wait_group %0;" :: "n"(n) : "memory")

__global__ void prep_kernel(const float* __restrict__ wq, const float* __restrict__ wk,
                            const float* __restrict__ wv, const float* __restrict__ projw,
                            const float* __restrict__ fc1w, const float* __restrict__ fc2w) {
    int stride = gridDim.x * blockDim.x;
    int t0 = blockIdx.x * blockDim.x + threadIdx.x;

    for (int idx = t0; idx < 24 * 2 * 32 * 4; idx += stride) {
        int c = idx & 3, lane = (idx >> 2) & 31, u = (idx >> 7) & 1, nt = idx >> 8;
        int kk = 2 * u + (c >> 1), j = c & 1;
        int n = nt * 8 + (lane >> 2);
        int kb = kk * 16 + 2 * (lane & 3) + 8 * j;
        float v0, v1;
        if (n < 64)       { int h = n >> 3, d = n & 7; v0 = wq[(h * 64 + kb) * 8 + d]; v1 = wq[(h * 64 + kb + 1) * 8 + d]; }
        else if (n < 128) { int m = n - 64;  int h = m >> 3, d = m & 7; v0 = wk[(h * 64 + kb) * 8 + d]; v1 = wk[(h * 64 + kb + 1) * 8 + d]; }
        else              { int m = n - 128; int h = m >> 3, d = m & 7; v0 = wv[(h * 64 + kb) * 8 + d]; v1 = wv[(h * 64 + kb + 1) * 8 + d]; }
        g_wqkvP[idx] = packbf(v0, v1);
    }
    for (int idx = t0; idx < 8 * 2 * 32 * 4; idx += stride) {
        int c = idx & 3, lane = (idx >> 2) & 31, u = (idx >> 7) & 1, nt = idx >> 8;
        int kk = 2 * u + (c >> 1), j = c & 1;
        int n = nt * 8 + (lane >> 2);
        int kb = kk * 16 + 2 * (lane & 3) + 8 * j;
        g_projP[idx] = packbf(projw[kb * 64 + n], projw[(kb + 1) * 64 + n]);
    }
    for (int idx = t0; idx < 32 * 2 * 32 * 4; idx += stride) {
        int c = idx & 3, lane = (idx >> 2) & 31, u = (idx >> 7) & 1, nt = idx >> 8;
        int kk = 2 * u + (c >> 1), j = c & 1;
        int n = nt * 8 + (lane >> 2);
        int kb = kk * 16 + 2 * (lane & 3) + 8 * j;
        g_fc1P[idx] = packbf(fc1w[kb * 256 + n], fc1w[(kb + 1) * 256 + n]);
    }
    for (int idx = t0; idx < 8 * 8 * 32 * 4; idx += stride) {
        int c = idx & 3, lane = (idx >> 2) & 31, u = (idx >> 7) & 7, nt = idx >> 10;
        int kk = 2 * u + (c >> 1), j = c & 1;
        int n = nt * 8 + (lane >> 2);
        int kb = kk * 16 + 2 * (lane & 3) + 8 * j;
        g_fc2P[idx] = packbf(fc2w[kb * 64 + n], fc2w[(kb + 1) * 64 + n]);
    }
}

__device__ __forceinline__ void mma16816(float* c, const uint32_t* a, const uint32_t* b) {
    asm volatile(
        "mma.sync.aligned.m16n8k16.row.col.f32.bf16.bf16.f32 "
        "{%0,%1,%2,%3}, {%4,%5,%6,%7}, {%8,%9}, {%0,%1,%2,%3};\n"
        : "+f"(c[0]), "+f"(c[1]), "+f"(c[2]), "+f"(c[3])
        : "r"(a[0]), "r"(a[1]), "r"(a[2]), "r"(a[3]), "r"(b[0]), "r"(b[1]));
}

__device__ __forceinline__ void mma1688(float* c, const uint32_t* a, uint32_t b) {
    asm volatile(
        "mma.sync.aligned.m16n8k8.row.col.f32.bf16.bf16.f32 "
        "{%0,%1,%2,%3}, {%4,%5}, {%6}, {%0,%1,%2,%3};\n"
        : "+f"(c[0]), "+f"(c[1]), "+f"(c[2]), "+f"(c[3])
        : "r"(a[0]), "r"(a[1]), "r"(b));
}

// Register LayerNorm over fragment-resident residual (rows m0+g, m0+g+8; 4-lane qd groups).
__device__ __forceinline__ void ln_frag(const float xres[2][8][2],
                                        const float* __restrict__ lnw,
                                        const float* __restrict__ lnb,
                                        int qd, uint32_t a[4][4]) {
    float s0 = 0.f, q0 = 0.f, s1 = 0.f, q1 = 0.f;
#pragma unroll
    for (int nt = 0; nt < 8; ++nt) {
#pragma unroll
        for (int e = 0; e < 2; ++e) {
            float v0 = xres[0][nt][e], v1 = xres[1][nt][e];
            s0 += v0; q0 = fmaf(v0, v0, q0);
            s1 += v1; q1 = fmaf(v1, v1, q1);
        }
    }
    s0 += __shfl_xor_sync(0xffffffffu, s0, 1); s0 += __shfl_xor_sync(0xffffffffu, s0, 2);
    q0 += __shfl_xor_sync(0xffffffffu, q0, 1); q0 += __shfl_xor_sync(0xffffffffu, q0, 2);
    s1 += __shfl_xor_sync(0xffffffffu, s1, 1); s1 += __shfl_xor_sync(0xffffffffu, s1, 2);
    q1 += __shfl_xor_sync(0xffffffffu, q1, 1); q1 += __shfl_xor_sync(0xffffffffu, q1, 2);
    float mu0 = s0 * 0.015625f, mu1 = s1 * 0.015625f;
    float rs0 = rsqrtf(q0 * 0.015625f - mu0 * mu0 + 1e-5f);
    float rs1 = rsqrtf(q1 * 0.015625f - mu1 * mu1 + 1e-5f);
#pragma unroll
    for (int kk = 0; kk < 4; ++kk) {
#pragma unroll
        for (int j = 0; j < 2; ++j) {
            int nt = 2 * kk + j;
            float2 wv = __ldg(reinterpret_cast<const float2*>(&lnw[nt * 8 + 2 * qd]));
            float2 bv = __ldg(reinterpret_cast<const float2*>(&lnb[nt * 8 + 2 * qd]));
            a[kk][2 * j]     = packbf((xres[0][nt][0] - mu0) * rs0 * wv.x + bv.x,
                                      (xres[0][nt][1] - mu0) * rs0 * wv.y + bv.y);
            a[kk][2 * j + 1] = packbf((xres[1][nt][0] - mu1) * rs1 * wv.x + bv.x,
                                      (xres[1][nt][1] - mu1) * rs1 * wv.y + bv.y);
        }
    }
}

__global__ __launch_bounds__(THREADS, 2) void block_kernel(
    const float* __restrict__ x,
    const float* __restrict__ ln1w, const float* __restrict__ ln1b,
    const float* __restrict__ projb,
    const float* __restrict__ ln2w, const float* __restrict__ ln2b,
    const float* __restrict__ fc1b, const float* __restrict__ fc2b,
    float* __restrict__ out)
{
    extern __shared__ char smraw[];
    float* stage       = reinterpret_cast<float*>(smraw);                    // [128][68] f32
    __nv_bfloat16* scr = reinterpret_cast<__nv_bfloat16*>(smraw);            // [128][136] (aliases stage)
    __nv_bfloat16* vt  = reinterpret_cast<__nv_bfloat16*>(smraw + VT_OFF);   // [2][8][8][72]

    const int tid  = threadIdx.x;
    const int w    = tid >> 5;
    const int lane = tid & 31;
    const int g    = lane >> 2;
    const int qd   = lane & 3;
    const int s    = blockIdx.x;          // covers seqs 2s, 2s+1
    const int seqw = w >> 2;              // GEMM-phase sequence of this warp
    const int m0   = seqw * 64 + (w & 3) * 16;   // row in 0..127

    const uint32_t sA = smem_u32(smraw + WA_OFF);
    const uint32_t sB = smem_u32(smraw + WB_OFF);

    // ---- prefetch group 0: qkv + proj -> WA ----
#pragma unroll
    for (int i = 0; i < 6; ++i)
        cp16(sA + (tid + i * 256) * 16, (const char*)g_wqkvP + (tid + i * 256) * 16);
#pragma unroll
    for (int i = 0; i < 2; ++i)
        cp16(sA + 24576 + (tid + i * 256) * 16, (const char*)g_projP + (tid + i * 256) * 16);
    CP_COMMIT();
    // ---- prefetch group 1: fc1 half 0 -> WB ----
#pragma unroll
    for (int i = 0; i < 4; ++i)
        cp16(sB + (tid + i * 256) * 16, (const char*)g_fc1P + (tid + i * 256) * 16);
    CP_COMMIT();

    // ---- stage x for both seqs ----
    {
        const float4* xg = reinterpret_cast<const float4*>(x + (size_t)s * 128 * 64);
        int row = tid >> 1, c0 = (tid & 1) * 32;
#pragma unroll
        for (int i = 0; i < 8; ++i) {
            float4 v = xg[row * 16 + (c0 >> 2) + i];
            *reinterpret_cast<float4*>(&stage[row * ST_S + c0 + 4 * i]) = v;
        }
    }
    __syncthreads();

    // ---- hoist residual into fragment registers ----
    float xres[2][8][2];
#pragma unroll
    for (int nt = 0; nt < 8; ++nt) {
        float2 v0 = *reinterpret_cast<const float2*>(&stage[(m0 + g)     * ST_S + nt * 8 + 2 * qd]);
        float2 v1 = *reinterpret_cast<const float2*>(&stage[(m0 + g + 8) * ST_S + nt * 8 + 2 * qd]);
        xres[0][nt][0] = v0.x; xres[0][nt][1] = v0.y;
        xres[1][nt][0] = v1.x; xres[1][nt][1] = v1.y;
    }
    CP_WAIT(1);        // WA (qkv+proj) resident
    __syncthreads();   // stage dead; WA visible

    // ---- LN1 (registers) -> QKV A fragments ----
    uint32_t a[4][4];
    ln_frag(xres, ln1w, ln1b, qd, a);

    // ---- QKV GEMM (weights from WA): q(pre-scaled)/k -> scr, v -> vt ----
    {
        const int t0r = (w & 3) * 16;   // row-within-seq base for V transpose
#pragma unroll 4
        for (int nt = 0; nt < 24; ++nt) {
            uint4 b01 = *reinterpret_cast<const uint4*>(smraw + WA_OFF + (nt * 64 + lane) * 16);
            uint4 b23 = *reinterpret_cast<const uint4*>(smraw + WA_OFF + (nt * 64 + 32 + lane) * 16);
            float c[4] = {0.f, 0.f, 0.f, 0.f};
            mma16816(c, a[0], &b01.x);
            mma16816(c, a[1], &b01.z);
            mma16816(c, a[2], &b23.x);
            mma16816(c, a[3], &b23.z);
            if (nt < 8) {
                int n0 = nt * 8;
                *reinterpret_cast<uint32_t*>(&scr[(m0 + g)     * SCR_S + n0 + 2 * qd]) =
                    packbf(c[0] * QSCALE, c[1] * QSCALE);
                *reinterpret_cast<uint32_t*>(&scr[(m0 + g + 8) * SCR_S + n0 + 2 * qd]) =
                    packbf(c[2] * QSCALE, c[3] * QSCALE);
            } else if (nt < 16) {
                int n0 = 64 + (nt - 8) * 8;
                *reinterpret_cast<uint32_t*>(&scr[(m0 + g)     * SCR_S + n0 + 2 * qd]) = packbf(c[0], c[1]);
                *reinterpret_cast<uint32_t*>(&scr[(m0 + g + 8) * SCR_S + n0 + 2 * qd]) = packbf(c[2], c[3]);
            } else {
                int head = nt - 16;
                __nv_bfloat16* vh = vt + (seqw * 8 + head) * 8 * VT_S;
                vh[(2 * qd)     * VT_S + t0r + g]     = __float2bfloat16(c[0]);
                vh[(2 * qd + 1) * VT_S + t0r + g]     = __float2bfloat16(c[1]);
                vh[(2 * qd)     * VT_S + t0r + g + 8] = __float2bfloat16(c[2]);
                vh[(2 * qd + 1) * VT_S + t0r + g + 8] = __float2bfloat16(c[3]);
            }
        }
    }
    __syncthreads();   // qkv weights dead

    // ---- prefetch group 2: fc2 first 24KB -> WA[0,24576) (window = attention + proj) ----
#pragma unroll
    for (int i = 0; i < 6; ++i)
        cp16(sA + (tid + i * 256) * 16, (const char*)g_fc2P + (tid + i * 256) * 16);
    CP_COMMIT();

    // ---- attention: warp handles head-seqs 2w, 2w+1 (16 total); attn-out IN PLACE over q ----
#pragma unroll
    for (int hh = 0; hh < 2; ++hh) {
        const int hs = w * 2 + hh;            // 0..15
        const int aseq = hs >> 3, hd = hs & 7;
        const int qb = aseq * 64;             // scr row base for this seq
        const int qcol = hd * 8, kcol = 64 + hd * 8;
        const __nv_bfloat16* vh = vt + (aseq * 8 + hd) * 8 * VT_S;
#pragma unroll
        for (int mt = 0; mt < 4; ++mt) {
            const int t0 = mt * 16;
            const int ntm = 2 * mt + 1;
            uint32_t aq[2];
            aq[0] = *reinterpret_cast<const uint32_t*>(&scr[(qb + t0 + g)     * SCR_S + qcol + 2 * qd]);
            aq[1] = *reinterpret_cast<const uint32_t*>(&scr[(qb + t0 + g + 8) * SCR_S + qcol + 2 * qd]);
            float sc[8][4];
#pragma unroll
            for (int nt = 0; nt < 8; ++nt) {
                if (nt > ntm) continue;
                sc[nt][0] = sc[nt][1] = sc[nt][2] = sc[nt][3] = 0.f;
                uint32_t bk = *reinterpret_cast<const uint32_t*>(&scr[(qb + nt * 8 + g) * SCR_S + kcol + 2 * qd]);
                mma1688(sc[nt], aq, bk);
            }
            const int rlo = t0 + g, rhi = t0 + g + 8;
            float slo = 0.f, shi = 0.f;
#pragma unroll
            for (int nt = 0; nt < 8; ++nt) {
                if (nt > ntm) continue;
#pragma unroll
                for (int e = 0; e < 2; ++e) {
                    int col = nt * 8 + 2 * qd + e;
                    float p0 = (col <= rlo) ? ex2(sc[nt][e])     : 0.f;
                    float p1 = (col <= rhi) ? ex2(sc[nt][2 + e]) : 0.f;
                    sc[nt][e] = p0; sc[nt][2 + e] = p1;
                    slo += p0; shi += p1;
                }
            }
            slo += __shfl_xor_sync(0xffffffffu, slo, 1);
            slo += __shfl_xor_sync(0xffffffffu, slo, 2);
            shi += __shfl_xor_sync(0xffffffffu, shi, 1);
            shi += __shfl_xor_sync(0xffffffffu, shi, 2);
            float acc[4] = {0.f, 0.f, 0.f, 0.f};
#pragma unroll
            for (int kc = 0; kc < 4; ++kc) {
                if (kc > mt) continue;
                uint32_t pa[4];
                pa[0] = packbf(sc[2 * kc][0],     sc[2 * kc][1]);
                pa[1] = packbf(sc[2 * kc][2],     sc[2 * kc][3]);
                pa[2] = packbf(sc[2 * kc + 1][0], sc[2 * kc + 1][1]);
                pa[3] = packbf(sc[2 * kc + 1][2], sc[2 * kc + 1][3]);
                const int sb = kc * 16;
                uint32_t b[2];
                b[0] = *reinterpret_cast<const uint32_t*>(&vh[g * VT_S + sb + 2 * qd]);
                b[1] = *reinterpret_cast<const uint32_t*>(&vh[g * VT_S + sb + 2 * qd + 8]);
                mma16816(acc, pa, b);
            }
            float ilo = 1.f / slo, ihi = 1.f / shi;
            *reinterpret_cast<uint32_t*>(&scr[(qb + t0 + g)     * SCR_S + qcol + 2 * qd]) = packbf(acc[0] * ilo, acc[1] * ilo);
            *reinterpret_cast<uint32_t*>(&scr[(qb + t0 + g + 8) * SCR_S + qcol + 2 * qd]) = packbf(acc[2] * ihi, acc[3] * ihi);
        }
    }
    __syncthreads();

    // ---- proj + residual into xres (registers); weights from WA[24576,32768) ----
    {
        uint32_t ap[4][4];
#pragma unroll
        for (int kk = 0; kk < 4; ++kk) {
            int k0 = kk * 16;
            ap[kk][0] = *reinterpret_cast<const uint32_t*>(&scr[(m0 + g)     * SCR_S + k0 + 2 * qd]);
            ap[kk][1] = *reinterpret_cast<const uint32_t*>(&scr[(m0 + g + 8) * SCR_S + k0 + 2 * qd]);
            ap[kk][2] = *reinterpret_cast<const uint32_t*>(&scr[(m0 + g)     * SCR_S + k0 + 2 * qd + 8]);
            ap[kk][3] = *reinterpret_cast<const uint32_t*>(&scr[(m0 + g + 8) * SCR_S + k0 + 2 * qd + 8]);
        }
#pragma unroll
        for (int nt = 0; nt < 8; ++nt) {
            uint4 b01 = *reinterpret_cast<const uint4*>(smraw + WA_OFF + 24576 + (nt * 64 + lane) * 16);
            uint4 b23 = *reinterpret_cast<const uint4*>(smraw + WA_OFF + 24576 + (nt * 64 + 32 + lane) * 16);
            float c[4] = {0.f, 0.f, 0.f, 0.f};
            mma16816(c, ap[0], &b01.x);
            mma16816(c, ap[1], &b01.z);
            mma16816(c, ap[2], &b23.x);
            mma16816(c, ap[3], &b23.z);
            float2 pb = __ldg(reinterpret_cast<const float2*>(&projb[nt * 8 + 2 * qd]));
            xres[0][nt][0] += c[0] + pb.x; xres[0][nt][1] += c[1] + pb.y;
            xres[1][nt][0] += c[2] + pb.x; xres[1][nt][1] += c[3] + pb.y;
        }
    }
    __syncthreads();   // proj weights + scr reads done

    // ---- prefetch group 3: fc2 last 8KB -> WA[24576,32768) ----
#pragma unroll
    for (int i = 0; i < 2; ++i)
        cp16(sA + 24576 + (tid + i * 256) * 16, (const char*)g_fc2P + 24576 + (tid + i * 256) * 16);
    CP_COMMIT();

    // ---- LN2 (registers) -> fc1 A fragments ----
    uint32_t a2[4][4];
    ln_frag(xres, ln2w, ln2b, qd, a2);

    // ---- spill xres to stage (scr dead; self-read only, no barrier needed) ----
#pragma unroll
    for (int nt = 0; nt < 8; ++nt) {
        float2 v0, v1;
        v0.x = xres[0][nt][0]; v0.y = xres[0][nt][1];
        v1.x = xres[1][nt][0]; v1.y = xres[1][nt][1];
        *reinterpret_cast<float2*>(&stage[(m0 + g)     * ST_S + nt * 8 + 2 * qd]) = v0;
        *reinterpret_cast<float2*>(&stage[(m0 + g + 8) * ST_S + nt * 8 + 2 * qd]) = v1;
    }

    CP_WAIT(0);        // fc1.h0 (WB) + fc2 (WA) resident
    __syncthreads();

    // ---- fc phase, double-buffered fc1 halves in WB ----
    float cfc2[8][4];
#pragma unroll
    for (int i = 0; i < 8; ++i) { cfc2[i][0] = cfc2[i][1] = cfc2[i][2] = cfc2[i][3] = 0.f; }

    uint32_t apk8[8][4];
    // ===== half 0: fc1 nt 0..15 from WB =====
#pragma unroll
    for (int kkL = 0; kkL < 8; ++kkL) {
#pragma unroll
        for (int half = 0; half < 2; ++half) {
            int nt = 2 * kkL + half;
            uint4 b01 = *reinterpret_cast<const uint4*>(smraw + WB_OFF + (nt * 64 + lane) * 16);
            uint4 b23 = *reinterpret_cast<const uint4*>(smraw + WB_OFF + (nt * 64 + 32 + lane) * 16);
            float c[4] = {0.f, 0.f, 0.f, 0.f};
            mma16816(c, a2[0], &b01.x);
            mma16816(c, a2[1], &b01.z);
            mma16816(c, a2[2], &b23.x);
            mma16816(c, a2[3], &b23.z);
            float2 fb = __ldg(reinterpret_cast<const float2*>(&fc1b[nt * 8 + 2 * qd]));
            apk8[kkL][2 * half]     = packbf(fmaxf(c[0] + fb.x, 0.f), fmaxf(c[1] + fb.y, 0.f));
            apk8[kkL][2 * half + 1] = packbf(fmaxf(c[2] + fb.x, 0.f), fmaxf(c[3] + fb.y, 0.f));
        }
    }
    __syncthreads();   // all warps done reading fc1.h0 from WB
    // prefetch fc1 half 1 -> WB (covered by fc2-partial h0 compute)
#pragma unroll
    for (int i = 0; i < 4; ++i)
        cp16(sB + (tid + i * 256) * 16, (const char*)g_fc1P + 16384 + (tid + i * 256) * 16);
    CP_COMMIT();
    // fc2 partial, h2 = 0 (u groups 0..3)
#pragma unroll
    for (int nt2 = 0; nt2 < 8; ++nt2) {
#pragma unroll
        for (int u = 0; u < 4; ++u) {
            uint4 bb = *reinterpret_cast<const uint4*>(
                smraw + WA_OFF + ((nt2 * 8 + u) * 32 + lane) * 16);
            mma16816(cfc2[nt2], apk8[2 * u],     &bb.x);
            mma16816(cfc2[nt2], apk8[2 * u + 1], &bb.z);
        }
    }
    CP_WAIT(0);
    __syncthreads();   // fc1.h1 resident

    // ===== half 1: fc1 nt 16..31 from WB =====
#pragma unroll
    for (int kkL = 0; kkL < 8; ++kkL) {
#pragma unroll
        for (int half = 0; half < 2; ++half) {
            int nt = 16 + 2 * kkL + half;
            uint4 b01 = *reinterpret_cast<const uint4*>(smraw + WB_OFF + ((nt - 16) * 64 + lane) * 16);
            uint4 b23 = *reinterpret_cast<const uint4*>(smraw + WB_OFF + ((nt - 16) * 64 + 32 + lane) * 16);
            float c[4] = {0.f, 0.f, 0.f, 0.f};
            mma16816(c, a2[0], &b01.x);
            mma16816(c, a2[1], &b01.z);
            mma16816(c, a2[2], &b23.x);
            mma16816(c, a2[3], &b23.z);
            float2 fb = __ldg(reinterpret_cast<const float2*>(&fc1b[nt * 8 + 2 * qd]));
            apk8[kkL][2 * half]     = packbf(fmaxf(c[0] + fb.x, 0.f), fmaxf(c[1] + fb.y, 0.f));
            apk8[kkL][2 * half + 1] = packbf(fmaxf(c[2] + fb.x, 0.f), fmaxf(c[3] + fb.y, 0.f));
        }
    }
    // fc2 partial, h2 = 1 (u groups 4..7)
#pragma unroll
    for (int nt2 = 0; nt2 < 8; ++nt2) {
#pragma unroll
        for (int u = 0; u < 4; ++u) {
            uint4 bb = *reinterpret_cast<const uint4*>(
                smraw + WA_OFF + ((nt2 * 8 + 4 + u) * 32 + lane) * 16);
            mma16816(cfc2[nt2], apk8[2 * u],     &bb.x);
            mma16816(cfc2[nt2], apk8[2 * u + 1], &bb.z);
        }
    }

    // ---- fc2 epilogue: + bias + residual (from smem spill) -> out ----
    {
#pragma unroll
        for (int nt = 0; nt < 8; ++nt) {
            int c0 = nt * 8 + 2 * qd;
            float2 fb = __ldg(reinterpret_cast<const float2*>(&fc2b[c0]));
            float2 x0 = *reinterpret_cast<const float2*>(&stage[(m0 + g)     * ST_S + c0]);
            float2 x1 = *reinterpret_cast<const float2*>(&stage[(m0 + g + 8) * ST_S + c0]);
            float2 o0, o1;
            o0.x = cfc2[nt][0] + fb.x + x0.x;
            o0.y = cfc2[nt][1] + fb.y + x0.y;
            o1.x = cfc2[nt][2] + fb.x + x1.x;
            o1.y = cfc2[nt][3] + fb.y + x1.y;
            *reinterpret_cast<float2*>(out + ((size_t)s * 128 + m0 + g)     * 64 + c0) = o0;
            *reinterpret_cast<float2*>(out + ((size_t)s * 128 + m0 + g + 8) * 64 + c0) = o1;
        }
    }
}

extern "C" void kernel_launch(void* const* d_in, const int* in_sizes, int n_in,
                              void* d_out, int out_size) {
    (void)in_sizes; (void)n_in; (void)out_size;
    const float* x     = (const float*)d_in[0];
    const float* ln1w  = (const float*)d_in[1];
    const float* ln1b  = (const float*)d_in[2];
    const float* wq    = (const float*)d_in[3];
    const float* wk    = (const float*)d_in[4];
    const float* wv    = (const float*)d_in[5];
    const float* projw = (const float*)d_in[6];
    const float* projb = (const float*)d_in[7];
    const float* ln2w  = (const float*)d_in[8];
    const float* ln2b  = (const float*)d_in[9];
    const float* fc1w  = (const float*)d_in[10];
    const float* fc1b  = (const float*)d_in[11];
    const float* fc2w  = (const float*)d_in[12];
    const float* fc2b  = (const float*)d_in[13];

    cudaFuncSetAttribute(block_kernel, cudaFuncAttributeMaxDynamicSharedMemorySize, SMEM_BYTES);
    cudaFuncSetAttribute(block_kernel, cudaFuncAttributePreferredSharedMemoryCarveout, 100);

    prep_kernel<<<32, 256>>>(wq, wk, wv, projw, fc1w, fc2w);
    block_kernel<<<NCTA, THREADS, SMEM_BYTES>>>(x, ln1w, ln1b, projb, ln2w, ln2b,
                                                fc1b, fc2b, (float*)d_out);
}

// round 16
// speedup vs baseline: 1.0129x; 1.0127x over previous
#include <cuda_runtime.h>
#include <cuda_bf16.h>
#include <stdint.h>

#define SEQS 4096
#define NCTA 2048
#define THREADS 256

// Dynamic smem layout (bytes):
//  [0,34816)        f32 stage[128][68] (x staging / xres spill) -> bf16 scr[128][136] q|attn (0..63), k (64..127)
//  [34816,53248)    bf16 vt[2][8][8][72]  V transposed; reused after attention for fc2 nt2 6,7 (8KB)
//  [53248,86016)    WA: qkv packed (24576B) + proj packed (8192B); qkv region reused for fc2 nt2 0..5 (24KB)
//  [86016,102400)   WB: fc1 half-buffer (16384B, double-buffered h0 -> h1)
#define ST_S 68
#define SCR_S 136
#define VT_S 72
#define VT_OFF 34816
#define WA_OFF 53248
#define WB_OFF 86016
#define SMEM_BYTES 102400

// q pre-scale: (1/8) * log2(e); softmax uses exp2
#define QSCALE 0.1803368801111204f

// Fragment-packed bf16 weights (same layout as prior rounds):
//   [nt][u][lane][c]; kk = 2u + (c>>1), j = c&1; n = nt*8 + (lane>>2); k = kk*16 + 2*(lane&3) + 8*j
__device__ __align__(16) uint32_t g_wqkvP[24 * 2 * 32 * 4];   // 24576 B
__device__ __align__(16) uint32_t g_projP[8 * 2 * 32 * 4];    // 8192 B
__device__ __align__(16) uint32_t g_fc1P[32 * 2 * 32 * 4];    // 32768 B
__device__ __align__(16) uint32_t g_fc2P[8 * 8 * 32 * 4];     // 32768 B ([nt2] major, 4096B each)

__device__ __forceinline__ uint32_t packbf(float lo, float hi) {
    __nv_bfloat162 t = __floats2bfloat162_rn(lo, hi);
    return *reinterpret_cast<uint32_t*>(&t);
}

__device__ __forceinline__ float ex2(float x) {
    float r; asm("ex2.approx.f32 %0, %1;" : "=f"(r) : "f"(x)); return r;
}

__device__ __forceinline__ uint32_t smem_u32(const void* p) {
    uint32_t a;
    asm("{ .reg .u64 t; cvta.to.shared.u64 t, %1; cvt.u32.u64 %0, t; }" : "=r"(a) : "l"(p));
    return a;
}

__device__ __forceinline__ void cp16(uint32_t dst, const void* src) {
    asm volatile("cp.async.cg.shared.global [%0], [%1], 16;" :: "r"(dst), "l"(src) : "memory");
}
#define CP_COMMIT() asm volatile("cp.async.commit_group;" ::: "memory")
#define CP_WAIT(n)  asm volatile("cp.async.wait_group %0;" :: "n"(n) : "memory")

__global__ void prep_kernel(const float* __restrict__ wq, const float* __restrict__ wk,
                            const float* __restrict__ wv, const float* __restrict__ projw,
                            const float* __restrict__ fc1w, const float* __restrict__ fc2w) {
    int stride = gridDim.x * blockDim.x;
    int t0 = blockIdx.x * blockDim.x + threadIdx.x;

    for (int idx = t0; idx < 24 * 2 * 32 * 4; idx += stride) {
        int c = idx & 3, lane = (idx >> 2) & 31, u = (idx >> 7) & 1, nt = idx >> 8;
        int kk = 2 * u + (c >> 1), j = c & 1;
        int n = nt * 8 + (lane >> 2);
        int kb = kk * 16 + 2 * (lane & 3) + 8 * j;
        float v0, v1;
        if (n < 64)       { int h = n >> 3, d = n & 7; v0 = wq[(h * 64 + kb) * 8 + d]; v1 = wq[(h * 64 + kb + 1) * 8 + d]; }
        else if (n < 128) { int m = n - 64;  int h = m >> 3, d = m & 7; v0 = wk[(h * 64 + kb) * 8 + d]; v1 = wk[(h * 64 + kb + 1) * 8 + d]; }
        else              { int m = n - 128; int h = m >> 3, d = m & 7; v0 = wv[(h * 64 + kb) * 8 + d]; v1 = wv[(h * 64 + kb + 1) * 8 + d]; }
        g_wqkvP[idx] = packbf(v0, v1);
    }
    for (int idx = t0; idx < 8 * 2 * 32 * 4; idx += stride) {
        int c = idx & 3, lane = (idx >> 2) & 31, u = (idx >> 7) & 1, nt = idx >> 8;
        int kk = 2 * u + (c >> 1), j = c & 1;
        int n = nt * 8 + (lane >> 2);
        int kb = kk * 16 + 2 * (lane & 3) + 8 * j;
        g_projP[idx] = packbf(projw[kb * 64 + n], projw[(kb + 1) * 64 + n]);
    }
    for (int idx = t0; idx < 32 * 2 * 32 * 4; idx += stride) {
        int c = idx & 3, lane = (idx >> 2) & 31, u = (idx >> 7) & 1, nt = idx >> 8;
        int kk = 2 * u + (c >> 1), j = c & 1;
        int n = nt * 8 + (lane >> 2);
        int kb = kk * 16 + 2 * (lane & 3) + 8 * j;
        g_fc1P[idx] = packbf(fc1w[kb * 256 + n], fc1w[(kb + 1) * 256 + n]);
    }
    for (int idx = t0; idx < 8 * 8 * 32 * 4; idx += stride) {
        int c = idx & 3, lane = (idx >> 2) & 31, u = (idx >> 7) & 7, nt = idx >> 10;
        int kk = 2 * u + (c >> 1), j = c & 1;
        int n = nt * 8 + (lane >> 2);
        int kb = kk * 16 + 2 * (lane & 3) + 8 * j;
        g_fc2P[idx] = packbf(fc2w[kb * 64 + n], fc2w[(kb + 1) * 64 + n]);
    }
}

__device__ __forceinline__ void mma16816(float* c, const uint32_t* a, const uint32_t* b) {
    asm volatile(
        "mma.sync.aligned.m16n8k16.row.col.f32.bf16.bf16.f32 "
        "{%0,%1,%2,%3}, {%4,%5,%6,%7}, {%8,%9}, {%0,%1,%2,%3};\n"
        : "+f"(c[0]), "+f"(c[1]), "+f"(c[2]), "+f"(c[3])
        : "r"(a[0]), "r"(a[1]), "r"(a[2]), "r"(a[3]), "r"(b[0]), "r"(b[1]));
}

__device__ __forceinline__ void mma1688(float* c, const uint32_t* a, uint32_t b) {
    asm volatile(
        "mma.sync.aligned.m16n8k8.row.col.f32.bf16.bf16.f32 "
        "{%0,%1,%2,%3}, {%4,%5}, {%6}, {%0,%1,%2,%3};\n"
        : "+f"(c[0]), "+f"(c[1]), "+f"(c[2]), "+f"(c[3])
        : "r"(a[0]), "r"(a[1]), "r"(b));
}

// Register LayerNorm over fragment-resident residual.
__device__ __forceinline__ void ln_frag(const float xres[2][8][2],
                                        const float* __restrict__ lnw,
                                        const float* __restrict__ lnb,
                                        int qd, uint32_t a[4][4]) {
    float s0 = 0.f, q0 = 0.f, s1 = 0.f, q1 = 0.f;
#pragma unroll
    for (int nt = 0; nt < 8; ++nt) {
#pragma unroll
        for (int e = 0; e < 2; ++e) {
            float v0 = xres[0][nt][e], v1 = xres[1][nt][e];
            s0 += v0; q0 = fmaf(v0, v0, q0);
            s1 += v1; q1 = fmaf(v1, v1, q1);
        }
    }
    s0 += __shfl_xor_sync(0xffffffffu, s0, 1); s0 += __shfl_xor_sync(0xffffffffu, s0, 2);
    q0 += __shfl_xor_sync(0xffffffffu, q0, 1); q0 += __shfl_xor_sync(0xffffffffu, q0, 2);
    s1 += __shfl_xor_sync(0xffffffffu, s1, 1); s1 += __shfl_xor_sync(0xffffffffu, s1, 2);
    q1 += __shfl_xor_sync(0xffffffffu, q1, 1); q1 += __shfl_xor_sync(0xffffffffu, q1, 2);
    float mu0 = s0 * 0.015625f, mu1 = s1 * 0.015625f;
    float rs0 = rsqrtf(q0 * 0.015625f - mu0 * mu0 + 1e-5f);
    float rs1 = rsqrtf(q1 * 0.015625f - mu1 * mu1 + 1e-5f);
#pragma unroll
    for (int kk = 0; kk < 4; ++kk) {
#pragma unroll
        for (int j = 0; j < 2; ++j) {
            int nt = 2 * kk + j;
            float2 wv = __ldg(reinterpret_cast<const float2*>(&lnw[nt * 8 + 2 * qd]));
            float2 bv = __ldg(reinterpret_cast<const float2*>(&lnb[nt * 8 + 2 * qd]));
            a[kk][2 * j]     = packbf((xres[0][nt][0] - mu0) * rs0 * wv.x + bv.x,
                                      (xres[0][nt][1] - mu0) * rs0 * wv.y + bv.y);
            a[kk][2 * j + 1] = packbf((xres[1][nt][0] - mu1) * rs1 * wv.x + bv.x,
                                      (xres[1][nt][1] - mu1) * rs1 * wv.y + bv.y);
        }
    }
}

__global__ __launch_bounds__(THREADS, 2) void block_kernel(
    const float* __restrict__ x,
    const float* __restrict__ ln1w, const float* __restrict__ ln1b,
    const float* __restrict__ projb,
    const float* __restrict__ ln2w, const float* __restrict__ ln2b,
    const float* __restrict__ fc1b, const float* __restrict__ fc2b,
    float* __restrict__ out)
{
    extern __shared__ char smraw[];
    float* stage       = reinterpret_cast<float*>(smraw);                    // [128][68] f32
    __nv_bfloat16* scr = reinterpret_cast<__nv_bfloat16*>(smraw);            // [128][136] (aliases stage)
    __nv_bfloat16* vt  = reinterpret_cast<__nv_bfloat16*>(smraw + VT_OFF);   // [2][8][8][72]

    const int tid  = threadIdx.x;
    const int w    = tid >> 5;
    const int lane = tid & 31;
    const int g    = lane >> 2;
    const int qd   = lane & 3;
    const int s    = blockIdx.x;
    const int seqw = w >> 2;
    const int m0   = seqw * 64 + (w & 3) * 16;

    const uint32_t sA = smem_u32(smraw + WA_OFF);
    const uint32_t sB = smem_u32(smraw + WB_OFF);
    const uint32_t sV = smem_u32(smraw + VT_OFF);

    // ---- prefetch group 0: qkv + proj -> WA ----
#pragma unroll
    for (int i = 0; i < 6; ++i)
        cp16(sA + (tid + i * 256) * 16, (const char*)g_wqkvP + (tid + i * 256) * 16);
#pragma unroll
    for (int i = 0; i < 2; ++i)
        cp16(sA + 24576 + (tid + i * 256) * 16, (const char*)g_projP + (tid + i * 256) * 16);
    CP_COMMIT();
    // ---- prefetch group 1: fc1 half 0 -> WB ----
#pragma unroll
    for (int i = 0; i < 4; ++i)
        cp16(sB + (tid + i * 256) * 16, (const char*)g_fc1P + (tid + i * 256) * 16);
    CP_COMMIT();

    // ---- stage x for both seqs ----
    {
        const float4* xg = reinterpret_cast<const float4*>(x + (size_t)s * 128 * 64);
        int row = tid >> 1, c0 = (tid & 1) * 32;
#pragma unroll
        for (int i = 0; i < 8; ++i) {
            float4 v = xg[row * 16 + (c0 >> 2) + i];
            *reinterpret_cast<float4*>(&stage[row * ST_S + c0 + 4 * i]) = v;
        }
    }
    __syncthreads();

    // ---- hoist residual into fragment registers ----
    float xres[2][8][2];
#pragma unroll
    for (int nt = 0; nt < 8; ++nt) {
        float2 v0 = *reinterpret_cast<const float2*>(&stage[(m0 + g)     * ST_S + nt * 8 + 2 * qd]);
        float2 v1 = *reinterpret_cast<const float2*>(&stage[(m0 + g + 8) * ST_S + nt * 8 + 2 * qd]);
        xres[0][nt][0] = v0.x; xres[0][nt][1] = v0.y;
        xres[1][nt][0] = v1.x; xres[1][nt][1] = v1.y;
    }
    CP_WAIT(1);        // WA (qkv+proj) resident
    __syncthreads();   // stage dead; WA visible

    // ---- LN1 (registers) -> QKV A fragments ----
    uint32_t a[4][4];
    ln_frag(xres, ln1w, ln1b, qd, a);

    // ---- QKV GEMM (weights from WA): q(pre-scaled)/k -> scr, v -> vt ----
    {
        const int t0r = (w & 3) * 16;
#pragma unroll 4
        for (int nt = 0; nt < 24; ++nt) {
            uint4 b01 = *reinterpret_cast<const uint4*>(smraw + WA_OFF + (nt * 64 + lane) * 16);
            uint4 b23 = *reinterpret_cast<const uint4*>(smraw + WA_OFF + (nt * 64 + 32 + lane) * 16);
            float c[4] = {0.f, 0.f, 0.f, 0.f};
            mma16816(c, a[0], &b01.x);
            mma16816(c, a[1], &b01.z);
            mma16816(c, a[2], &b23.x);
            mma16816(c, a[3], &b23.z);
            if (nt < 8) {
                int n0 = nt * 8;
                *reinterpret_cast<uint32_t*>(&scr[(m0 + g)     * SCR_S + n0 + 2 * qd]) =
                    packbf(c[0] * QSCALE, c[1] * QSCALE);
                *reinterpret_cast<uint32_t*>(&scr[(m0 + g + 8) * SCR_S + n0 + 2 * qd]) =
                    packbf(c[2] * QSCALE, c[3] * QSCALE);
            } else if (nt < 16) {
                int n0 = 64 + (nt - 8) * 8;
                *reinterpret_cast<uint32_t*>(&scr[(m0 + g)     * SCR_S + n0 + 2 * qd]) = packbf(c[0], c[1]);
                *reinterpret_cast<uint32_t*>(&scr[(m0 + g + 8) * SCR_S + n0 + 2 * qd]) = packbf(c[2], c[3]);
            } else {
                int head = nt - 16;
                __nv_bfloat16* vh = vt + (seqw * 8 + head) * 8 * VT_S;
                vh[(2 * qd)     * VT_S + t0r + g]     = __float2bfloat16(c[0]);
                vh[(2 * qd + 1) * VT_S + t0r + g]     = __float2bfloat16(c[1]);
                vh[(2 * qd)     * VT_S + t0r + g + 8] = __float2bfloat16(c[2]);
                vh[(2 * qd + 1) * VT_S + t0r + g + 8] = __float2bfloat16(c[3]);
            }
        }
    }
    __syncthreads();   // qkv weights dead

    // ---- prefetch group 2: fc2 nt2 0..5 (24KB) -> WA[0,24576) ----
#pragma unroll
    for (int i = 0; i < 6; ++i)
        cp16(sA + (tid + i * 256) * 16, (const char*)g_fc2P + (tid + i * 256) * 16);
    CP_COMMIT();

    // ---- attention: warp handles head-seqs 2w, 2w+1; k/v register-cached per head ----
#pragma unroll
    for (int hh = 0; hh < 2; ++hh) {
        const int hs = w * 2 + hh;
        const int aseq = hs >> 3, hd = hs & 7;
        const int qb = aseq * 64;
        const int qcol = hd * 8, kcol = 64 + hd * 8;
        const __nv_bfloat16* vh = vt + (aseq * 8 + hd) * 8 * VT_S;
        // cache k fragments (mt-invariant) and v fragments
        uint32_t kf[8], vf0[4], vf1[4];
#pragma unroll
        for (int nt = 0; nt < 8; ++nt)
            kf[nt] = *reinterpret_cast<const uint32_t*>(&scr[(qb + nt * 8 + g) * SCR_S + kcol + 2 * qd]);
#pragma unroll
        for (int kc = 0; kc < 4; ++kc) {
            vf0[kc] = *reinterpret_cast<const uint32_t*>(&vh[g * VT_S + kc * 16 + 2 * qd]);
            vf1[kc] = *reinterpret_cast<const uint32_t*>(&vh[g * VT_S + kc * 16 + 2 * qd + 8]);
        }
#pragma unroll
        for (int mt = 0; mt < 4; ++mt) {
            const int t0 = mt * 16;
            const int ntm = 2 * mt + 1;
            uint32_t aq[2];
            aq[0] = *reinterpret_cast<const uint32_t*>(&scr[(qb + t0 + g)     * SCR_S + qcol + 2 * qd]);
            aq[1] = *reinterpret_cast<const uint32_t*>(&scr[(qb + t0 + g + 8) * SCR_S + qcol + 2 * qd]);
            float sc[8][4];
#pragma unroll
            for (int nt = 0; nt < 8; ++nt) {
                if (nt > ntm) continue;
                sc[nt][0] = sc[nt][1] = sc[nt][2] = sc[nt][3] = 0.f;
                mma1688(sc[nt], aq, kf[nt]);
            }
            const int rlo = t0 + g, rhi = t0 + g + 8;
            float slo = 0.f, shi = 0.f;
#pragma unroll
            for (int nt = 0; nt < 8; ++nt) {
                if (nt > ntm) continue;
#pragma unroll
                for (int e = 0; e < 2; ++e) {
                    int col = nt * 8 + 2 * qd + e;
                    float p0 = (col <= rlo) ? ex2(sc[nt][e])     : 0.f;
                    float p1 = (col <= rhi) ? ex2(sc[nt][2 + e]) : 0.f;
                    sc[nt][e] = p0; sc[nt][2 + e] = p1;
                    slo += p0; shi += p1;
                }
            }
            slo += __shfl_xor_sync(0xffffffffu, slo, 1);
            slo += __shfl_xor_sync(0xffffffffu, slo, 2);
            shi += __shfl_xor_sync(0xffffffffu, shi, 1);
            shi += __shfl_xor_sync(0xffffffffu, shi, 2);
            float acc[4] = {0.f, 0.f, 0.f, 0.f};
#pragma unroll
            for (int kc = 0; kc < 4; ++kc) {
                if (kc > mt) continue;
                uint32_t pa[4];
                pa[0] = packbf(sc[2 * kc][0],     sc[2 * kc][1]);
                pa[1] = packbf(sc[2 * kc][2],     sc[2 * kc][3]);
                pa[2] = packbf(sc[2 * kc + 1][0], sc[2 * kc + 1][1]);
                pa[3] = packbf(sc[2 * kc + 1][2], sc[2 * kc + 1][3]);
                uint32_t b[2] = { vf0[kc], vf1[kc] };
                mma16816(acc, pa, b);
            }
            float ilo = 1.f / slo, ihi = 1.f / shi;
            *reinterpret_cast<uint32_t*>(&scr[(qb + t0 + g)     * SCR_S + qcol + 2 * qd]) = packbf(acc[0] * ilo, acc[1] * ilo);
            *reinterpret_cast<uint32_t*>(&scr[(qb + t0 + g + 8) * SCR_S + qcol + 2 * qd]) = packbf(acc[2] * ihi, acc[3] * ihi);
        }
    }
    __syncthreads();   // attention done; vt dead

    // ---- prefetch group 3: fc2 nt2 6,7 (8KB) -> vt region ----
#pragma unroll
    for (int i = 0; i < 2; ++i)
        cp16(sV + (tid + i * 256) * 16, (const char*)g_fc2P + 24576 + (tid + i * 256) * 16);
    CP_COMMIT();

    // ---- proj + residual into xres (own rows only); weights from WA[24576,32768) ----
    {
        uint32_t ap[4][4];
#pragma unroll
        for (int kk = 0; kk < 4; ++kk) {
            int k0 = kk * 16;
            ap[kk][0] = *reinterpret_cast<const uint32_t*>(&scr[(m0 + g)     * SCR_S + k0 + 2 * qd]);
            ap[kk][1] = *reinterpret_cast<const uint32_t*>(&scr[(m0 + g + 8) * SCR_S + k0 + 2 * qd]);
            ap[kk][2] = *reinterpret_cast<const uint32_t*>(&scr[(m0 + g)     * SCR_S + k0 + 2 * qd + 8]);
            ap[kk][3] = *reinterpret_cast<const uint32_t*>(&scr[(m0 + g + 8) * SCR_S + k0 + 2 * qd + 8]);
        }
#pragma unroll
        for (int nt = 0; nt < 8; ++nt) {
            uint4 b01 = *reinterpret_cast<const uint4*>(smraw + WA_OFF + 24576 + (nt * 64 + lane) * 16);
            uint4 b23 = *reinterpret_cast<const uint4*>(smraw + WA_OFF + 24576 + (nt * 64 + 32 + lane) * 16);
            float c[4] = {0.f, 0.f, 0.f, 0.f};
            mma16816(c, ap[0], &b01.x);
            mma16816(c, ap[1], &b01.z);
            mma16816(c, ap[2], &b23.x);
            mma16816(c, ap[3], &b23.z);
            float2 pb = __ldg(reinterpret_cast<const float2*>(&projb[nt * 8 + 2 * qd]));
            xres[0][nt][0] += c[0] + pb.x; xres[0][nt][1] += c[1] + pb.y;
            xres[1][nt][0] += c[2] + pb.x; xres[1][nt][1] += c[3] + pb.y;
        }
    }

    // ---- LN2 (registers) -> fc1 A fragments ----
    uint32_t a2[4][4];
    ln_frag(xres, ln2w, ln2b, qd, a2);

    // ---- spill xres to stage (own rows; proj already read them in program order) ----
#pragma unroll
    for (int nt = 0; nt < 8; ++nt) {
        float2 v0, v1;
        v0.x = xres[0][nt][0]; v0.y = xres[0][nt][1];
        v1.x = xres[1][nt][0]; v1.y = xres[1][nt][1];
        *reinterpret_cast<float2*>(&stage[(m0 + g)     * ST_S + nt * 8 + 2 * qd]) = v0;
        *reinterpret_cast<float2*>(&stage[(m0 + g + 8) * ST_S + nt * 8 + 2 * qd]) = v1;
    }

    CP_WAIT(0);        // fc1.h0 (WB) + fc2 (WA + vt) resident
    __syncthreads();

    // ---- fc phase, double-buffered fc1 halves in WB ----
    float cfc2[8][4];
#pragma unroll
    for (int i = 0; i < 8; ++i) { cfc2[i][0] = cfc2[i][1] = cfc2[i][2] = cfc2[i][3] = 0.f; }

    uint32_t apk8[8][4];
    // ===== half 0: fc1 nt 0..15 from WB =====
#pragma unroll
    for (int kkL = 0; kkL < 8; ++kkL) {
#pragma unroll
        for (int half = 0; half < 2; ++half) {
            int nt = 2 * kkL + half;
            uint4 b01 = *reinterpret_cast<const uint4*>(smraw + WB_OFF + (nt * 64 + lane) * 16);
            uint4 b23 = *reinterpret_cast<const uint4*>(smraw + WB_OFF + (nt * 64 + 32 + lane) * 16);
            float c[4] = {0.f, 0.f, 0.f, 0.f};
            mma16816(c, a2[0], &b01.x);
            mma16816(c, a2[1], &b01.z);
            mma16816(c, a2[2], &b23.x);
            mma16816(c, a2[3], &b23.z);
            float2 fb = __ldg(reinterpret_cast<const float2*>(&fc1b[nt * 8 + 2 * qd]));
            apk8[kkL][2 * half]     = packbf(fmaxf(c[0] + fb.x, 0.f), fmaxf(c[1] + fb.y, 0.f));
            apk8[kkL][2 * half + 1] = packbf(fmaxf(c[2] + fb.x, 0.f), fmaxf(c[3] + fb.y, 0.f));
        }
    }
    __syncthreads();   // fc1.h0 reads done
    // prefetch fc1 half 1 -> WB
#pragma unroll
    for (int i = 0; i < 4; ++i)
        cp16(sB + (tid + i * 256) * 16, (const char*)g_fc1P + 16384 + (tid + i * 256) * 16);
    CP_COMMIT();
    // fc2 partial, u 0..3
#pragma unroll
    for (int nt2 = 0; nt2 < 8; ++nt2) {
        const char* f2b = (nt2 < 6) ? (smraw + WA_OFF + nt2 * 4096)
                                    : (smraw + VT_OFF + (nt2 - 6) * 4096);
#pragma unroll
        for (int u = 0; u < 4; ++u) {
            uint4 bb = *reinterpret_cast<const uint4*>(f2b + (u * 32 + lane) * 16);
            mma16816(cfc2[nt2], apk8[2 * u],     &bb.x);
            mma16816(cfc2[nt2], apk8[2 * u + 1], &bb.z);
        }
    }
    CP_WAIT(0);
    __syncthreads();   // fc1.h1 resident

    // ===== half 1: fc1 nt 16..31 from WB =====
#pragma unroll
    for (int kkL = 0; kkL < 8; ++kkL) {
#pragma unroll
        for (int half = 0; half < 2; ++half) {
            int nt = 16 + 2 * kkL + half;
            uint4 b01 = *reinterpret_cast<const uint4*>(smraw + WB_OFF + ((nt - 16) * 64 + lane) * 16);
            uint4 b23 = *reinterpret_cast<const uint4*>(smraw + WB_OFF + ((nt - 16) * 64 + 32 + lane) * 16);
            float c[4] = {0.f, 0.f, 0.f, 0.f};
            mma16816(c, a2[0], &b01.x);
            mma16816(c, a2[1], &b01.z);
            mma16816(c, a2[2], &b23.x);
            mma16816(c, a2[3], &b23.z);
            float2 fb = __ldg(reinterpret_cast<const float2*>(&fc1b[nt * 8 + 2 * qd]));
            apk8[kkL][2 * half]     = packbf(fmaxf(c[0] + fb.x, 0.f), fmaxf(c[1] + fb.y, 0.f));
            apk8[kkL][2 * half + 1] = packbf(fmaxf(c[2] + fb.x, 0.f), fmaxf(c[3] + fb.y, 0.f));
        }
    }
    // fc2 partial, u 4..7
#pragma unroll
    for (int nt2 = 0; nt2 < 8; ++nt2) {
        const char* f2b = (nt2 < 6) ? (smraw + WA_OFF + nt2 * 4096)
                                    : (smraw + VT_OFF + (nt2 - 6) * 4096);
#pragma unroll
        for (int u = 0; u < 4; ++u) {
            uint4 bb = *reinterpret_cast<const uint4*>(f2b + ((4 + u) * 32 + lane) * 16);
            mma16816(cfc2[nt2], apk8[2 * u],     &bb.x);
            mma16816(cfc2[nt2], apk8[2 * u + 1], &bb.z);
        }
    }

    // ---- fc2 epilogue: + bias + residual (from smem spill) -> out ----
    {
#pragma unroll
        for (int nt = 0; nt < 8; ++nt) {
            int c0 = nt * 8 + 2 * qd;
            float2 fb = __ldg(reinterpret_cast<const float2*>(&fc2b[c0]));
            float2 x0 = *reinterpret_cast<const float2*>(&stage[(m0 + g)     * ST_S + c0]);
            float2 x1 = *reinterpret_cast<const float2*>(&stage[(m0 + g + 8) * ST_S + c0]);
            float2 o0, o1;
            o0.x = cfc2[nt][0] + fb.x + x0.x;
            o0.y = cfc2[nt][1] + fb.y + x0.y;
            o1.x = cfc2[nt][2] + fb.x + x1.x;
            o1.y = cfc2[nt][3] + fb.y + x1.y;
            *reinterpret_cast<float2*>(out + ((size_t)s * 128 + m0 + g)     * 64 + c0) = o0;
            *reinterpret_cast<float2*>(out + ((size_t)s * 128 + m0 + g + 8) * 64 + c0) = o1;
        }
    }
}

extern "C" void kernel_launch(void* const* d_in, const int* in_sizes, int n_in,
                              void* d_out, int out_size) {
    (void)in_sizes; (void)n_in; (void)out_size;
    const float* x     = (const float*)d_in[0];
    const float* ln1w  = (const float*)d_in[1];
    const float* ln1b  = (const float*)d_in[2];
    const float* wq    = (const float*)d_in[3];
    const float* wk    = (const float*)d_in[4];
    const float* wv    = (const float*)d_in[5];
    const float* projw = (const float*)d_in[6];
    const float* projb = (const float*)d_in[7];
    const float* ln2w  = (const float*)d_in[8];
    const float* ln2b  = (const float*)d_in[9];
    const float* fc1w  = (const float*)d_in[10];
    const float* fc1b  = (const float*)d_in[11];
    const float* fc2w  = (const float*)d_in[12];
    const float* fc2b  = (const float*)d_in[13];

    cudaFuncSetAttribute(block_kernel, cudaFuncAttributeMaxDynamicSharedMemorySize, SMEM_BYTES);
    cudaFuncSetAttribute(block_kernel, cudaFuncAttributePreferredSharedMemoryCarveout, 100);

    prep_kernel<<<32, 256>>>(wq, wk, wv, projw, fc1w, fc2w);
    block_kernel<<<NCTA, THREADS, SMEM_BYTES>>>(x, ln1w, ln1b, projb, ln2w, ln2b,
                                                fc1b, fc2b, (float*)d_out);
}